// round 16
// baseline (speedup 1.0000x reference)
#include <cuda_runtime.h>
#include <math.h>
#include <stdint.h>

#define BQ 2
#define SQ 2048
#define DQ 1024
#define HQ 16
#define DHQ 64
#define FQ 4096
#define MQ (BQ*SQ)   // 4096 rows

// ---------------- scratch (device globals; no allocation allowed) ----------------
__device__ float g_u  [MQ*DQ];
__device__ float g_Q  [BQ*HQ*SQ*DHQ];
__device__ float g_Kr [BQ*HQ*DHQ*SQ];
__device__ float g_V  [BQ*HQ*SQ*DHQ];
__device__ float g_hc [MQ*DQ];
__device__ float g_z1 [MQ*DQ];
__device__ float g_v1 [MQ*DQ];
__device__ float g_v3 [MQ*FQ];
__device__ float g_WOt [DQ*DQ];
__device__ float g_Wupt[FQ*DQ];
__device__ float g_Wdnt[DQ*FQ];
__device__ float g_Wqkv[3*DQ*DQ];   // rounded [3072,1024]: rows 0-1023 Q, 1024-2047 K, 2048-3071 V

// ---------------- helpers ----------------
__device__ __forceinline__ uint32_t smem_u32(const void* p){
    uint32_t a;
    asm("{ .reg .u64 t; cvta.to.shared.u64 t, %1; cvt.u32.u64 %0, t; }" : "=r"(a) : "l"(p));
    return a;
}
__device__ __forceinline__ float rnd_tf32(float x){
    uint32_t r;
    asm("cvt.rna.tf32.f32 %0, %1;" : "=r"(r) : "f"(x));
    return __uint_as_float(r);
}
__device__ __forceinline__ float gelu_exact(float x){
    return 0.5f * x * (1.0f + erff(x * 0.70710678118654752f));
}
__device__ __forceinline__ void mma_tf32(float* c, const uint32_t* a, const uint32_t* b){
    asm volatile("mma.sync.aligned.m16n8k8.row.col.f32.tf32.tf32.f32 "
        "{%0,%1,%2,%3}, {%4,%5,%6,%7}, {%8,%9}, {%0,%1,%2,%3};"
        : "+f"(c[0]), "+f"(c[1]), "+f"(c[2]), "+f"(c[3])
        : "r"(a[0]), "r"(a[1]), "r"(a[2]), "r"(a[3]), "r"(b[0]), "r"(b[1]));
}
#define LDSM_X4(r0, r1, r2, r3, addr) \
    asm volatile("ldmatrix.sync.aligned.m8n8.x4.shared.b16 {%0,%1,%2,%3}, [%4];" \
        : "=r"(r0), "=r"(r1), "=r"(r2), "=r"(r3) : "r"(addr))
#define CP16(d, s)  asm volatile("cp.async.cg.shared.global [%0], [%1], 16;" :: "r"(d), "l"(s) : "memory")
#define CP_COMMIT   asm volatile("cp.async.commit_group;" ::: "memory")
#define CP_WAIT0    asm volatile("cp.async.wait_group 0;" ::: "memory")
#define CP_WAIT1    asm volatile("cp.async.wait_group 1;" ::: "memory")

// ---------------- LayerNorm (tf32-rounded output) ----------------
__global__ __launch_bounds__(256) void ln_kernel(const float* __restrict__ x,
                                                 const float* __restrict__ gamma,
                                                 const float* __restrict__ beta,
                                                 float* __restrict__ out)
{
    int row = blockIdx.x;
    int t = threadIdx.x;
    const float4* xr = (const float4*)(x + (size_t)row * DQ);
    float4 v = xr[t];
    float s  = v.x + v.y + v.z + v.w;
    float s2 = v.x*v.x + v.y*v.y + v.z*v.z + v.w*v.w;
    #pragma unroll
    for (int off = 16; off; off >>= 1){
        s  += __shfl_xor_sync(0xffffffffu, s,  off);
        s2 += __shfl_xor_sync(0xffffffffu, s2, off);
    }
    __shared__ float sm[8], sm2[8];
    int w = t >> 5, lane = t & 31;
    if (!lane){ sm[w] = s; sm2[w] = s2; }
    __syncthreads();
    if (t == 0){
        float a = 0.f, b = 0.f;
        #pragma unroll
        for (int i = 0; i < 8; i++){ a += sm[i]; b += sm2[i]; }
        sm[0] = a; sm2[0] = b;
    }
    __syncthreads();
    float mu  = sm[0]  * (1.0f / DQ);
    float var = sm2[0] * (1.0f / DQ) - mu * mu;
    float inv = rsqrtf(var + 1e-5f);
    float4 g  = ((const float4*)gamma)[t];
    float4 be = ((const float4*)beta)[t];
    float4 o;
    o.x = rnd_tf32((v.x - mu) * inv * g.x + be.x);
    o.y = rnd_tf32((v.y - mu) * inv * g.y + be.y);
    o.z = rnd_tf32((v.z - mu) * inv * g.z + be.z);
    o.w = rnd_tf32((v.w - mu) * inv * g.w + be.w);
    ((float4*)(out + (size_t)row * DQ))[t] = o;
}

// ---------------- transpose + tf32 round: out[C,R] = round(in[R,C]^T) ----------------
__global__ __launch_bounds__(256) void transpose_kernel(const float* __restrict__ in,
                                                        float* __restrict__ out,
                                                        int R, int Ccols)
{
    __shared__ float t[32][33];
    int c0 = blockIdx.x * 32, r0 = blockIdx.y * 32;
    int x = threadIdx.x, y = threadIdx.y;   // 32x8
    #pragma unroll
    for (int i = 0; i < 32; i += 8)
        t[y + i][x] = in[(size_t)(r0 + y + i) * Ccols + c0 + x];
    __syncthreads();
    #pragma unroll
    for (int i = 0; i < 32; i += 8)
        out[(size_t)(c0 + y + i) * R + r0 + x] = rnd_tf32(t[x][y + i]);
}

// ---------------- fused transpose of W_up and W_down (one launch) ----------------
__global__ __launch_bounds__(256) void transpose_updn_kernel(const float* __restrict__ wup,
                                                             float* __restrict__ wupt,
                                                             const float* __restrict__ wdn,
                                                             float* __restrict__ wdnt)
{
    __shared__ float t[32][33];
    const float* in;  float* out;  int R, Ccols, c0, r0;
    if (blockIdx.z == 0){
        in = wup;  out = wupt;  R = DQ; Ccols = FQ;
        c0 = blockIdx.x * 32;
        r0 = blockIdx.y * 32;
    } else {
        in = wdn;  out = wdnt;  R = FQ; Ccols = DQ;
        c0 = blockIdx.y * 32;
        r0 = blockIdx.x * 32;
    }
    int x = threadIdx.x, y = threadIdx.y;   // 32x8
    #pragma unroll
    for (int i = 0; i < 32; i += 8)
        t[y + i][x] = in[(size_t)(r0 + y + i) * Ccols + c0 + x];
    __syncthreads();
    #pragma unroll
    for (int i = 0; i < 32; i += 8)
        out[(size_t)(c0 + y + i) * R + r0 + x] = rnd_tf32(t[x][y + i]);
}

// ---------------- fused round copy of W_Q,W_K,W_V -> Wqkv[3072,1024] ----------------
__global__ __launch_bounds__(256) void round_copy_qkv(const float* __restrict__ wq,
                                                      const float* __restrict__ wk,
                                                      const float* __restrict__ wv,
                                                      float* __restrict__ out)
{
    int n4 = 3 * DQ * DQ / 4;
    int seg = DQ * DQ / 4;
    for (int i = blockIdx.x * blockDim.x + threadIdx.x; i < n4; i += gridDim.x * blockDim.x){
        const float* src = (i < seg) ? wq : (i < 2*seg) ? wk : wv;
        int j = (i < seg) ? i : (i < 2*seg) ? i - seg : i - 2*seg;
        float4 v = ((const float4*)src)[j];
        v.x = rnd_tf32(v.x); v.y = rnd_tf32(v.y);
        v.z = rnd_tf32(v.z); v.w = rnd_tf32(v.w);
        ((float4*)out)[i] = v;
    }
}

// ---------------- GEMM (R9 config): 512 threads, warp 64x32, 3-stage cp.async + ldmatrix ----------------
#define ST2 36
#define STAGE_F (384*ST2)
template<int MODE>
__global__ __launch_bounds__(512) void mma_gemm(
    const float* __restrict__ A, const float* __restrict__ Bt,
    float* __restrict__ C, int Mdim, int Ndim, int Kdim,
    const float* __restrict__ bias, const float* __restrict__ resid)
{
    extern __shared__ float sh[];

    int tid = threadIdx.x, wid = tid >> 5, lane = tid & 31;
    int grp = lane >> 2, tig = lane & 3;
    int wm0 = (wid & 3) << 6;
    int wn0 = (wid >> 2) << 5;
    int bm = blockIdx.y << 8, bn = blockIdx.x << 7;

    uint32_t sbase = smem_u32(sh);
    const float* aSrcBase = A  + (size_t)(bm + (tid >> 1)) * Kdim + (tid & 1) * 16;
    const float* bSrcBase = Bt + (size_t)(bn + (tid >> 2)) * Kdim + (tid & 3) * 8;
    uint32_t aOff = (tid >> 1) * (ST2*4) + (tid & 1) * 64;
    uint32_t bOff = 256*(ST2*4) + (tid >> 2) * (ST2*4) + (tid & 3) * 32;

    auto load_chunk = [&](int ch){
        int st = ch % 3;
        int k0 = ch << 5;
        uint32_t da = sbase + st * (STAGE_F*4) + aOff;
        const float* sa = aSrcBase + k0;
        #pragma unroll
        for (int j = 0; j < 4; j++) CP16(da + j*16, sa + j*4);
        uint32_t db = sbase + st * (STAGE_F*4) + bOff;
        const float* sb = bSrcBase + k0;
        #pragma unroll
        for (int j = 0; j < 2; j++) CP16(db + j*16, sb + j*4);
        CP_COMMIT;
    };

    int nc = Kdim >> 5;
    load_chunk(0);
    load_chunk(1);

    int lrow  = lane & 7;
    int lh8   = (lane >> 3) & 1;
    int lc4   = lane >> 4;
    uint32_t aLane[4], bLane[2];
    #pragma unroll
    for (int mt = 0; mt < 4; mt++)
        aLane[mt] = (uint32_t)(((wm0 + mt*16 + lrow + 8*lh8) * ST2 + 4*lc4) * 4);
    int bNt  = lane >> 4;
    int bC4  = (lane >> 3) & 1;
    #pragma unroll
    for (int p = 0; p < 2; p++)
        bLane[p] = (uint32_t)(256*ST2*4 + ((wn0 + (2*p + bNt)*8 + lrow) * ST2 + 4*bC4) * 4);

    float acc[4][4][4];
    #pragma unroll
    for (int mt = 0; mt < 4; mt++)
        #pragma unroll
        for (int nt = 0; nt < 4; nt++)
            #pragma unroll
            for (int q = 0; q < 4; q++) acc[mt][nt][q] = 0.f;

    for (int ch = 0; ch < nc; ch++){
        if (ch <= nc - 2) { CP_WAIT1; } else { CP_WAIT0; }
        __syncthreads();
        if (ch + 2 < nc) load_chunk(ch + 2);

        uint32_t stA = sbase + (ch % 3) * (STAGE_F*4);
        #pragma unroll
        for (int ks = 0; ks < 4; ks++){
            uint32_t kkb = (uint32_t)(ks * 32);
            uint32_t af[4][4], bf[4][2];
            #pragma unroll
            for (int mt = 0; mt < 4; mt++)
                LDSM_X4(af[mt][0], af[mt][1], af[mt][2], af[mt][3], stA + aLane[mt] + kkb);
            #pragma unroll
            for (int p = 0; p < 2; p++)
                LDSM_X4(bf[2*p][0], bf[2*p][1], bf[2*p+1][0], bf[2*p+1][1], stA + bLane[p] + kkb);
            #pragma unroll
            for (int mt = 0; mt < 4; mt++)
                #pragma unroll
                for (int nt = 0; nt < 4; nt++)
                    mma_tf32(acc[mt][nt], af[mt], bf[nt]);
        }
    }

    // -------- epilogue --------
    #pragma unroll
    for (int mt = 0; mt < 4; mt++){
        #pragma unroll
        for (int half = 0; half < 2; half++){
            int m = bm + wm0 + mt*16 + grp + half*8;
            #pragma unroll
            for (int nt = 0; nt < 4; nt++){
                int n = bn + wn0 + nt*8 + tig*2;
                float v0 = acc[mt][nt][half*2 + 0];
                float v1 = acc[mt][nt][half*2 + 1];
                if (MODE <= 3){
                    if (MODE == 1){
                        float2 r = *(const float2*)&resid[(size_t)m * Ndim + n];
                        v0 += r.x; v1 += r.y;
                    } else if (MODE == 2){
                        float2 bb = *(const float2*)&bias[n];
                        v0 = rnd_tf32(gelu_exact(v0 + bb.x));
                        v1 = rnd_tf32(gelu_exact(v1 + bb.y));
                    } else if (MODE == 3){
                        float2 bb = *(const float2*)&bias[n];
                        float2 r  = *(const float2*)&resid[(size_t)m * Ndim + n];
                        v0 += bb.x + r.x; v1 += bb.y + r.y;
                    }
                    *(float2*)&C[(size_t)m * Ndim + n] = make_float2(v0, v1);
                } else {
                    // MODE 6: fused QKV scatter. n in [0,3072).
                    v0 = rnd_tf32(v0); v1 = rnd_tf32(v1);
                    int which = n >> 10;
                    int nn = n & 1023;
                    int b = m >> 11, s = m & 2047;
                    int h = nn >> 6, e = nn & 63;
                    if (which == 0){
                        *(float2*)&C[(((size_t)b*HQ + h)*SQ + s)*DHQ + e] = make_float2(v0, v1);
                    } else if (which == 1){
                        int flat = s * DHQ + e;   // raw-reshape quirk
                        float* Kr = (float*)bias;
                        *(float2*)&Kr[(((size_t)b*HQ + h)*DHQ + (flat >> 11))*SQ + (flat & 2047)]
                            = make_float2(v0, v1);
                    } else {
                        float* Vp = (float*)resid;
                        *(float2*)&Vp[(((size_t)b*HQ + h)*SQ + s)*DHQ + e] = make_float2(v0, v1);
                    }
                }
            }
        }
    }
}
static const int GEMM_SMEM = 3 * STAGE_F * 4;   // 165888 B

// ---------------- tensor-core flash attention: 128 Q rows / 256 threads / 3 CTAs/SM ----------------
#define QST 68
#define KST 72
#define QR2 128
static const int ATTN_SMEM = (QR2*QST + 2*64*KST) * 4;         // 71680 B -> 3 CTAs/SM (24 warps)

__global__ __launch_bounds__(256) void attn_tc(const float* __restrict__ Q,
                                               const float* __restrict__ Kr,
                                               const float* __restrict__ V,
                                               float* __restrict__ hc)
{
    extern __shared__ float sh[];
    float* Qs = sh;                    // [QR2][QST]; reused as Ps after aq frags cached
    float* Ps = sh;                    // alias — Q tile is dead once aq is in registers
    float* Ks = sh + QR2*QST;          // [e][t] [64][KST]
    float* Vs = Ks + 64*KST;           // [t][e] [64][KST]

    int bh = blockIdx.y;
    int b = bh >> 4, h = bh & 15;
    int m0 = blockIdx.x << 7;          // 128 rows per CTA
    const float* Qbh = Q  + (size_t)bh * SQ * DHQ;
    const float* Kbh = Kr + (size_t)bh * DHQ * SQ;
    const float* Vbh = V  + (size_t)bh * SQ * DHQ;

    int tid = threadIdx.x, wid = tid >> 5, lane = tid & 31;
    int grp = lane >> 2, tig = lane & 3;
    int mr = wid*16 + grp;             // 0..127 (wid 0..7)

    for (int i = tid; i < QR2*16; i += 256){
        int r = i >> 4, c4 = i & 15;
        *(float4*)&Qs[r*QST + c4*4] = *(const float4*)&Qbh[(size_t)(m0 + r) * DHQ + c4*4];
    }
    __syncthreads();

    uint32_t aq[8][4];
    #pragma unroll
    for (int ks = 0; ks < 8; ks++){
        int kk = ks << 3;
        aq[ks][0] = __float_as_uint(Qs[mr*QST     + kk + tig]);
        aq[ks][1] = __float_as_uint(Qs[(mr+8)*QST + kk + tig]);
        aq[ks][2] = __float_as_uint(Qs[mr*QST     + kk + tig + 4]);
        aq[ks][3] = __float_as_uint(Qs[(mr+8)*QST + kk + tig + 4]);
    }

    float accO[8][4];
    #pragma unroll
    for (int nt = 0; nt < 8; nt++)
        #pragma unroll
        for (int q = 0; q < 4; q++) accO[nt][q] = 0.f;
    float mrow0 = -1e30f, mrow1 = -1e30f, lrow0 = 0.f, lrow1 = 0.f;
    const float scale = 1.0f / 1024.0f;

    for (int n0 = 0; n0 < SQ; n0 += 64){
        for (int i = tid; i < 64*16; i += 256){
            int r = i >> 4, c4 = i & 15;
            *(float4*)&Ks[r*KST + c4*4] = *(const float4*)&Kbh[(size_t)r * SQ + n0 + c4*4];
            *(float4*)&Vs[r*KST + c4*4] = *(const float4*)&Vbh[(size_t)(n0 + r) * DHQ + c4*4];
        }
        __syncthreads();

        float sacc[8][4];
        #pragma unroll
        for (int nt = 0; nt < 8; nt++)
            #pragma unroll
            for (int q = 0; q < 4; q++) sacc[nt][q] = 0.f;
        #pragma unroll
        for (int ks = 0; ks < 8; ks++){
            int kk = ks << 3;
            uint32_t bf[8][2];
            #pragma unroll
            for (int nt = 0; nt < 8; nt++){
                int nr = nt*8 + grp;
                bf[nt][0] = __float_as_uint(Ks[(kk + tig)*KST     + nr]);
                bf[nt][1] = __float_as_uint(Ks[(kk + tig + 4)*KST + nr]);
            }
            #pragma unroll
            for (int nt = 0; nt < 8; nt++)
                mma_tf32(sacc[nt], aq[ks], bf[nt]);
        }

        float mx0 = -1e30f, mx1 = -1e30f;
        #pragma unroll
        for (int nt = 0; nt < 8; nt++){
            sacc[nt][0] *= scale; sacc[nt][1] *= scale;
            sacc[nt][2] *= scale; sacc[nt][3] *= scale;
            mx0 = fmaxf(mx0, fmaxf(sacc[nt][0], sacc[nt][1]));
            mx1 = fmaxf(mx1, fmaxf(sacc[nt][2], sacc[nt][3]));
        }
        mx0 = fmaxf(mx0, __shfl_xor_sync(0xffffffffu, mx0, 1));
        mx0 = fmaxf(mx0, __shfl_xor_sync(0xffffffffu, mx0, 2));
        mx1 = fmaxf(mx1, __shfl_xor_sync(0xffffffffu, mx1, 1));
        mx1 = fmaxf(mx1, __shfl_xor_sync(0xffffffffu, mx1, 2));
        float mn0 = fmaxf(mrow0, mx0), mn1 = fmaxf(mrow1, mx1);
        float al0 = __expf(mrow0 - mn0), al1 = __expf(mrow1 - mn1);
        mrow0 = mn0; mrow1 = mn1;

        float ps0 = 0.f, ps1 = 0.f;
        #pragma unroll
        for (int nt = 0; nt < 8; nt++){
            float p0 = __expf(sacc[nt][0] - mn0);
            float p1 = __expf(sacc[nt][1] - mn0);
            float p2 = __expf(sacc[nt][2] - mn1);
            float p3 = __expf(sacc[nt][3] - mn1);
            ps0 += p0 + p1; ps1 += p2 + p3;
            int col = nt*8 + tig*2;
            *(float2*)&Ps[mr*QST + col]     = make_float2(rnd_tf32(p0), rnd_tf32(p1));
            *(float2*)&Ps[(mr+8)*QST + col] = make_float2(rnd_tf32(p2), rnd_tf32(p3));
        }
        ps0 += __shfl_xor_sync(0xffffffffu, ps0, 1);
        ps0 += __shfl_xor_sync(0xffffffffu, ps0, 2);
        ps1 += __shfl_xor_sync(0xffffffffu, ps1, 1);
        ps1 += __shfl_xor_sync(0xffffffffu, ps1, 2);
        lrow0 = lrow0 * al0 + ps0;
        lrow1 = lrow1 * al1 + ps1;
        #pragma unroll
        for (int nt = 0; nt < 8; nt++){
            accO[nt][0] *= al0; accO[nt][1] *= al0;
            accO[nt][2] *= al1; accO[nt][3] *= al1;
        }
        __syncwarp();

        #pragma unroll
        for (int ks = 0; ks < 8; ks++){
            int kk = ks << 3;
            uint32_t ap[4], bf[8][2];
            ap[0] = __float_as_uint(Ps[mr*QST     + kk + tig]);
            ap[1] = __float_as_uint(Ps[(mr+8)*QST + kk + tig]);
            ap[2] = __float_as_uint(Ps[mr*QST     + kk + tig + 4]);
            ap[3] = __float_as_uint(Ps[(mr+8)*QST + kk + tig + 4]);
            #pragma unroll
            for (int nt = 0; nt < 8; nt++){
                int nr = nt*8 + grp;
                bf[nt][0] = __float_as_uint(Vs[(kk + tig)*KST     + nr]);
                bf[nt][1] = __float_as_uint(Vs[(kk + tig + 4)*KST + nr]);
            }
            #pragma unroll
            for (int nt = 0; nt < 8; nt++)
                mma_tf32(accO[nt], ap, bf[nt]);
        }
        __syncthreads();
    }

    float inv0 = 1.0f / lrow0, inv1 = 1.0f / lrow1;
    int row0 = m0 + mr, row1 = row0 + 8;
    #pragma unroll
    for (int nt = 0; nt < 8; nt++){
        int e = nt*8 + tig*2;
        *(float2*)&hc[((size_t)b*SQ + row0)*DQ + h*64 + e] =
            make_float2(rnd_tf32(accO[nt][0]*inv0), rnd_tf32(accO[nt][1]*inv0));
        *(float2*)&hc[((size_t)b*SQ + row1)*DQ + h*64 + e] =
            make_float2(rnd_tf32(accO[nt][2]*inv1), rnd_tf32(accO[nt][3]*inv1));
    }
}

// ---------------- launch ----------------
extern "C" void kernel_launch(void* const* d_in, const int* in_sizes, int n_in,
                              void* d_out, int out_size)
{
    const float* x      = (const float*)d_in[0];
    const float* W_Q    = (const float*)d_in[1];
    const float* W_K    = (const float*)d_in[2];
    const float* W_V    = (const float*)d_in[3];
    const float* W_O    = (const float*)d_in[4];
    const float* W_up   = (const float*)d_in[5];
    const float* b_up   = (const float*)d_in[6];
    const float* W_down = (const float*)d_in[7];
    const float* b_down = (const float*)d_in[8];
    const float* gamma1 = (const float*)d_in[9];
    const float* beta1  = (const float*)d_in[10];
    const float* gamma2 = (const float*)d_in[11];
    const float* beta2  = (const float*)d_in[12];
    float* out = (float*)d_out;

    float *u, *Qp, *Krp, *Vp, *hcp, *z1, *v1, *v3, *WOt, *Wupt, *Wdnt, *Wqkv;
    cudaGetSymbolAddress((void**)&u,    g_u);
    cudaGetSymbolAddress((void**)&Qp,   g_Q);
    cudaGetSymbolAddress((void**)&Krp,  g_Kr);
    cudaGetSymbolAddress((void**)&Vp,   g_V);
    cudaGetSymbolAddress((void**)&hcp,  g_hc);
    cudaGetSymbolAddress((void**)&z1,   g_z1);
    cudaGetSymbolAddress((void**)&v1,   g_v1);
    cudaGetSymbolAddress((void**)&v3,   g_v3);
    cudaGetSymbolAddress((void**)&WOt,  g_WOt);
    cudaGetSymbolAddress((void**)&Wupt, g_Wupt);
    cudaGetSymbolAddress((void**)&Wdnt, g_Wdnt);
    cudaGetSymbolAddress((void**)&Wqkv, g_Wqkv);

    cudaFuncSetAttribute((const void*)mma_gemm<1>, cudaFuncAttributeMaxDynamicSharedMemorySize, GEMM_SMEM);
    cudaFuncSetAttribute((const void*)mma_gemm<2>, cudaFuncAttributeMaxDynamicSharedMemorySize, GEMM_SMEM);
    cudaFuncSetAttribute((const void*)mma_gemm<3>, cudaFuncAttributeMaxDynamicSharedMemorySize, GEMM_SMEM);
    cudaFuncSetAttribute((const void*)mma_gemm<6>, cudaFuncAttributeMaxDynamicSharedMemorySize, GEMM_SMEM);
    cudaFuncSetAttribute((const void*)attn_tc,     cudaFuncAttributeMaxDynamicSharedMemorySize, ATTN_SMEM);

    // prep
    round_copy_qkv<<<1024, 256>>>(W_Q, W_K, W_V, Wqkv);
    transpose_kernel<<<dim3(DQ/32, DQ/32), dim3(32,8)>>>(W_O, WOt, DQ, DQ);
    transpose_updn_kernel<<<dim3(FQ/32, DQ/32, 2), dim3(32,8)>>>(W_up, Wupt, W_down, Wdnt);
    ln_kernel<<<MQ, 256>>>(x, gamma1, beta1, u);

    // fused QKV projection
    mma_gemm<6><<<dim3(3*DQ/128, MQ/256), 512, GEMM_SMEM>>>(u, Wqkv, Qp, MQ, 3*DQ, DQ, Krp, Vp);
    // tensor-core flash attention (128 Q rows per CTA, 3 CTAs/SM)
    attn_tc<<<dim3(SQ/QR2, BQ*HQ), 256, ATTN_SMEM>>>(Qp, Krp, Vp, hcp);
    // O projection + residual x
    mma_gemm<1><<<dim3(DQ/128, MQ/256), 512, GEMM_SMEM>>>(hcp, WOt, z1, MQ, DQ, DQ, nullptr, x);
    // LN2
    ln_kernel<<<MQ, 256>>>(z1, gamma2, beta2, v1);
    // FFN up + bias + exact GELU
    mma_gemm<2><<<dim3(FQ/128, MQ/256), 512, GEMM_SMEM>>>(v1, Wupt, v3, MQ, FQ, DQ, b_up, nullptr);
    // FFN down + bias + residual z1 -> out
    mma_gemm<3><<<dim3(DQ/128, MQ/256), 512, GEMM_SMEM>>>(v3, Wdnt, out, MQ, DQ, FQ, b_down, z1);
}

// round 17
// speedup vs baseline: 1.1280x; 1.1280x over previous
#include <cuda_runtime.h>
#include <math.h>
#include <stdint.h>

#define BQ 2
#define SQ 2048
#define DQ 1024
#define HQ 16
#define DHQ 64
#define FQ 4096
#define MQ (BQ*SQ)   // 4096 rows

// ---------------- scratch (device globals; no allocation allowed) ----------------
__device__ float g_u  [MQ*DQ];
__device__ float g_Q  [BQ*HQ*SQ*DHQ];
__device__ float g_Kr [BQ*HQ*DHQ*SQ];
__device__ float g_V  [BQ*HQ*SQ*DHQ];
__device__ float g_hc [MQ*DQ];
__device__ float g_z1 [MQ*DQ];
__device__ float g_v1 [MQ*DQ];
__device__ float g_v3 [MQ*FQ];
__device__ float g_WOt [DQ*DQ];
__device__ float g_Wupt[FQ*DQ];
__device__ float g_Wdnt[DQ*FQ];
__device__ float g_Wqkv[3*DQ*DQ];   // rounded [3072,1024]: rows 0-1023 Q, 1024-2047 K, 2048-3071 V

// ---------------- helpers ----------------
__device__ __forceinline__ uint32_t smem_u32(const void* p){
    uint32_t a;
    asm("{ .reg .u64 t; cvta.to.shared.u64 t, %1; cvt.u32.u64 %0, t; }" : "=r"(a) : "l"(p));
    return a;
}
__device__ __forceinline__ float rnd_tf32(float x){
    uint32_t r;
    asm("cvt.rna.tf32.f32 %0, %1;" : "=r"(r) : "f"(x));
    return __uint_as_float(r);
}
__device__ __forceinline__ float gelu_exact(float x){
    return 0.5f * x * (1.0f + erff(x * 0.70710678118654752f));
}
__device__ __forceinline__ void mma_tf32(float* c, const uint32_t* a, const uint32_t* b){
    asm volatile("mma.sync.aligned.m16n8k8.row.col.f32.tf32.tf32.f32 "
        "{%0,%1,%2,%3}, {%4,%5,%6,%7}, {%8,%9}, {%0,%1,%2,%3};"
        : "+f"(c[0]), "+f"(c[1]), "+f"(c[2]), "+f"(c[3])
        : "r"(a[0]), "r"(a[1]), "r"(a[2]), "r"(a[3]), "r"(b[0]), "r"(b[1]));
}
#define LDSM_X4(r0, r1, r2, r3, addr) \
    asm volatile("ldmatrix.sync.aligned.m8n8.x4.shared.b16 {%0,%1,%2,%3}, [%4];" \
        : "=r"(r0), "=r"(r1), "=r"(r2), "=r"(r3) : "r"(addr))
#define CP16(d, s)  asm volatile("cp.async.cg.shared.global [%0], [%1], 16;" :: "r"(d), "l"(s) : "memory")
#define CP_COMMIT   asm volatile("cp.async.commit_group;" ::: "memory")
#define CP_WAIT0    asm volatile("cp.async.wait_group 0;" ::: "memory")
#define CP_WAIT1    asm volatile("cp.async.wait_group 1;" ::: "memory")

// ---------------- LayerNorm (tf32-rounded output) ----------------
__global__ __launch_bounds__(256) void ln_kernel(const float* __restrict__ x,
                                                 const float* __restrict__ gamma,
                                                 const float* __restrict__ beta,
                                                 float* __restrict__ out)
{
    int row = blockIdx.x;
    int t = threadIdx.x;
    const float4* xr = (const float4*)(x + (size_t)row * DQ);
    float4 v = xr[t];
    float s  = v.x + v.y + v.z + v.w;
    float s2 = v.x*v.x + v.y*v.y + v.z*v.z + v.w*v.w;
    #pragma unroll
    for (int off = 16; off; off >>= 1){
        s  += __shfl_xor_sync(0xffffffffu, s,  off);
        s2 += __shfl_xor_sync(0xffffffffu, s2, off);
    }
    __shared__ float sm[8], sm2[8];
    int w = t >> 5, lane = t & 31;
    if (!lane){ sm[w] = s; sm2[w] = s2; }
    __syncthreads();
    if (t == 0){
        float a = 0.f, b = 0.f;
        #pragma unroll
        for (int i = 0; i < 8; i++){ a += sm[i]; b += sm2[i]; }
        sm[0] = a; sm2[0] = b;
    }
    __syncthreads();
    float mu  = sm[0]  * (1.0f / DQ);
    float var = sm2[0] * (1.0f / DQ) - mu * mu;
    float inv = rsqrtf(var + 1e-5f);
    float4 g  = ((const float4*)gamma)[t];
    float4 be = ((const float4*)beta)[t];
    float4 o;
    o.x = rnd_tf32((v.x - mu) * inv * g.x + be.x);
    o.y = rnd_tf32((v.y - mu) * inv * g.y + be.y);
    o.z = rnd_tf32((v.z - mu) * inv * g.z + be.z);
    o.w = rnd_tf32((v.w - mu) * inv * g.w + be.w);
    ((float4*)(out + (size_t)row * DQ))[t] = o;
}

// ---------------- transpose + tf32 round: out[C,R] = round(in[R,C]^T) ----------------
__global__ __launch_bounds__(256) void transpose_kernel(const float* __restrict__ in,
                                                        float* __restrict__ out,
                                                        int R, int Ccols)
{
    __shared__ float t[32][33];
    int c0 = blockIdx.x * 32, r0 = blockIdx.y * 32;
    int x = threadIdx.x, y = threadIdx.y;   // 32x8
    #pragma unroll
    for (int i = 0; i < 32; i += 8)
        t[y + i][x] = in[(size_t)(r0 + y + i) * Ccols + c0 + x];
    __syncthreads();
    #pragma unroll
    for (int i = 0; i < 32; i += 8)
        out[(size_t)(c0 + y + i) * R + r0 + x] = rnd_tf32(t[x][y + i]);
}

// ---------------- fused transpose of W_up and W_down (one launch) ----------------
__global__ __launch_bounds__(256) void transpose_updn_kernel(const float* __restrict__ wup,
                                                             float* __restrict__ wupt,
                                                             const float* __restrict__ wdn,
                                                             float* __restrict__ wdnt)
{
    __shared__ float t[32][33];
    const float* in;  float* out;  int R, Ccols, c0, r0;
    if (blockIdx.z == 0){
        in = wup;  out = wupt;  R = DQ; Ccols = FQ;
        c0 = blockIdx.x * 32;
        r0 = blockIdx.y * 32;
    } else {
        in = wdn;  out = wdnt;  R = FQ; Ccols = DQ;
        c0 = blockIdx.y * 32;
        r0 = blockIdx.x * 32;
    }
    int x = threadIdx.x, y = threadIdx.y;   // 32x8
    #pragma unroll
    for (int i = 0; i < 32; i += 8)
        t[y + i][x] = in[(size_t)(r0 + y + i) * Ccols + c0 + x];
    __syncthreads();
    #pragma unroll
    for (int i = 0; i < 32; i += 8)
        out[(size_t)(c0 + y + i) * R + r0 + x] = rnd_tf32(t[x][y + i]);
}

// ---------------- fused round copy of W_Q,W_K,W_V -> Wqkv[3072,1024] ----------------
__global__ __launch_bounds__(256) void round_copy_qkv(const float* __restrict__ wq,
                                                      const float* __restrict__ wk,
                                                      const float* __restrict__ wv,
                                                      float* __restrict__ out)
{
    int n4 = 3 * DQ * DQ / 4;
    int seg = DQ * DQ / 4;
    for (int i = blockIdx.x * blockDim.x + threadIdx.x; i < n4; i += gridDim.x * blockDim.x){
        const float* src = (i < seg) ? wq : (i < 2*seg) ? wk : wv;
        int j = (i < seg) ? i : (i < 2*seg) ? i - seg : i - 2*seg;
        float4 v = ((const float4*)src)[j];
        v.x = rnd_tf32(v.x); v.y = rnd_tf32(v.y);
        v.z = rnd_tf32(v.z); v.w = rnd_tf32(v.w);
        ((float4*)out)[i] = v;
    }
}

// ---------------- GEMM (R9 config): 512 threads, warp 64x32, 3-stage cp.async + ldmatrix ----------------
// C = A[M,K] @ Bt[N,K]^T, CTA 256x128, 16 warps (4m x 4n). Inputs pre-rounded tf32.
// MODE: 1 +resid | 2 round(gelu(acc+bias)) | 3 acc+bias+resid
//       6 fused QKV scatter: C=Q [B,H,S,DH], bias=Kr quirky [B,H,DH,S], resid=V [B,H,S,DH]
#define ST2 36
#define STAGE_F (384*ST2)
template<int MODE>
__global__ __launch_bounds__(512) void mma_gemm(
    const float* __restrict__ A, const float* __restrict__ Bt,
    float* __restrict__ C, int Mdim, int Ndim, int Kdim,
    const float* __restrict__ bias, const float* __restrict__ resid)
{
    extern __shared__ float sh[];

    int tid = threadIdx.x, wid = tid >> 5, lane = tid & 31;
    int grp = lane >> 2, tig = lane & 3;
    int wm0 = (wid & 3) << 6;
    int wn0 = (wid >> 2) << 5;
    int bm = blockIdx.y << 8, bn = blockIdx.x << 7;

    uint32_t sbase = smem_u32(sh);
    const float* aSrcBase = A  + (size_t)(bm + (tid >> 1)) * Kdim + (tid & 1) * 16;
    const float* bSrcBase = Bt + (size_t)(bn + (tid >> 2)) * Kdim + (tid & 3) * 8;
    uint32_t aOff = (tid >> 1) * (ST2*4) + (tid & 1) * 64;
    uint32_t bOff = 256*(ST2*4) + (tid >> 2) * (ST2*4) + (tid & 3) * 32;

    auto load_chunk = [&](int ch){
        int st = ch % 3;
        int k0 = ch << 5;
        uint32_t da = sbase + st * (STAGE_F*4) + aOff;
        const float* sa = aSrcBase + k0;
        #pragma unroll
        for (int j = 0; j < 4; j++) CP16(da + j*16, sa + j*4);
        uint32_t db = sbase + st * (STAGE_F*4) + bOff;
        const float* sb = bSrcBase + k0;
        #pragma unroll
        for (int j = 0; j < 2; j++) CP16(db + j*16, sb + j*4);
        CP_COMMIT;
    };

    int nc = Kdim >> 5;
    load_chunk(0);
    load_chunk(1);

    int lrow  = lane & 7;
    int lh8   = (lane >> 3) & 1;
    int lc4   = lane >> 4;
    uint32_t aLane[4], bLane[2];
    #pragma unroll
    for (int mt = 0; mt < 4; mt++)
        aLane[mt] = (uint32_t)(((wm0 + mt*16 + lrow + 8*lh8) * ST2 + 4*lc4) * 4);
    int bNt  = lane >> 4;
    int bC4  = (lane >> 3) & 1;
    #pragma unroll
    for (int p = 0; p < 2; p++)
        bLane[p] = (uint32_t)(256*ST2*4 + ((wn0 + (2*p + bNt)*8 + lrow) * ST2 + 4*bC4) * 4);

    float acc[4][4][4];
    #pragma unroll
    for (int mt = 0; mt < 4; mt++)
        #pragma unroll
        for (int nt = 0; nt < 4; nt++)
            #pragma unroll
            for (int q = 0; q < 4; q++) acc[mt][nt][q] = 0.f;

    for (int ch = 0; ch < nc; ch++){
        if (ch <= nc - 2) { CP_WAIT1; } else { CP_WAIT0; }
        __syncthreads();
        // prefetch ch+2 into stage (ch+2)%3 == (ch-1)%3 — readers released by the barrier above
        if (ch + 2 < nc) load_chunk(ch + 2);

        uint32_t stA = sbase + (ch % 3) * (STAGE_F*4);
        #pragma unroll
        for (int ks = 0; ks < 4; ks++){
            uint32_t kkb = (uint32_t)(ks * 32);
            uint32_t af[4][4], bf[4][2];
            #pragma unroll
            for (int mt = 0; mt < 4; mt++)
                LDSM_X4(af[mt][0], af[mt][1], af[mt][2], af[mt][3], stA + aLane[mt] + kkb);
            #pragma unroll
            for (int p = 0; p < 2; p++)
                LDSM_X4(bf[2*p][0], bf[2*p][1], bf[2*p+1][0], bf[2*p+1][1], stA + bLane[p] + kkb);
            #pragma unroll
            for (int mt = 0; mt < 4; mt++)
                #pragma unroll
                for (int nt = 0; nt < 4; nt++)
                    mma_tf32(acc[mt][nt], af[mt], bf[nt]);
        }
    }

    // -------- epilogue --------
    #pragma unroll
    for (int mt = 0; mt < 4; mt++){
        #pragma unroll
        for (int half = 0; half < 2; half++){
            int m = bm + wm0 + mt*16 + grp + half*8;
            #pragma unroll
            for (int nt = 0; nt < 4; nt++){
                int n = bn + wn0 + nt*8 + tig*2;
                float v0 = acc[mt][nt][half*2 + 0];
                float v1 = acc[mt][nt][half*2 + 1];
                if (MODE <= 3){
                    if (MODE == 1){
                        float2 r = *(const float2*)&resid[(size_t)m * Ndim + n];
                        v0 += r.x; v1 += r.y;
                    } else if (MODE == 2){
                        float2 bb = *(const float2*)&bias[n];
                        v0 = rnd_tf32(gelu_exact(v0 + bb.x));
                        v1 = rnd_tf32(gelu_exact(v1 + bb.y));
                    } else if (MODE == 3){
                        float2 bb = *(const float2*)&bias[n];
                        float2 r  = *(const float2*)&resid[(size_t)m * Ndim + n];
                        v0 += bb.x + r.x; v1 += bb.y + r.y;
                    }
                    *(float2*)&C[(size_t)m * Ndim + n] = make_float2(v0, v1);
                } else {
                    // MODE 6: fused QKV scatter. n in [0,3072).
                    v0 = rnd_tf32(v0); v1 = rnd_tf32(v1);
                    int which = n >> 10;
                    int nn = n & 1023;
                    int b = m >> 11, s = m & 2047;
                    int h = nn >> 6, e = nn & 63;
                    if (which == 0){
                        *(float2*)&C[(((size_t)b*HQ + h)*SQ + s)*DHQ + e] = make_float2(v0, v1);
                    } else if (which == 1){
                        int flat = s * DHQ + e;   // raw-reshape quirk
                        float* Kr = (float*)bias;
                        *(float2*)&Kr[(((size_t)b*HQ + h)*DHQ + (flat >> 11))*SQ + (flat & 2047)]
                            = make_float2(v0, v1);
                    } else {
                        float* Vp = (float*)resid;
                        *(float2*)&Vp[(((size_t)b*HQ + h)*SQ + s)*DHQ + e] = make_float2(v0, v1);
                    }
                }
            }
        }
    }
}
static const int GEMM_SMEM = 3 * STAGE_F * 4;   // 165888 B

// ---------------- tensor-core flash attention (R9 exact: separate Qs/Ps, 64 rows, 128 thr) ----------------
#define QST 68
#define KST 72
static const int ATTN_SMEM = (2*64*QST + 2*64*KST) * 4;        // 71680 B

__global__ __launch_bounds__(128) void attn_tc(const float* __restrict__ Q,
                                               const float* __restrict__ Kr,
                                               const float* __restrict__ V,
                                               float* __restrict__ hc)
{
    extern __shared__ float sh[];
    float* Qs = sh;                    // [64][QST]
    float* Ps = Qs + 64*QST;           // [64][QST]
    float* Ks = Ps + 64*QST;           // [e][t] [64][KST]
    float* Vs = Ks + 64*KST;           // [t][e] [64][KST]

    int bh = blockIdx.y;
    int b = bh >> 4, h = bh & 15;
    int m0 = blockIdx.x << 6;
    const float* Qbh = Q  + (size_t)bh * SQ * DHQ;
    const float* Kbh = Kr + (size_t)bh * DHQ * SQ;
    const float* Vbh = V  + (size_t)bh * SQ * DHQ;

    int tid = threadIdx.x, wid = tid >> 5, lane = tid & 31;
    int grp = lane >> 2, tig = lane & 3;
    int mr = wid*16 + grp;

    for (int i = tid; i < 64*16; i += 128){
        int r = i >> 4, c4 = i & 15;
        *(float4*)&Qs[r*QST + c4*4] = *(const float4*)&Qbh[(size_t)(m0 + r) * DHQ + c4*4];
    }
    __syncthreads();

    uint32_t aq[8][4];
    #pragma unroll
    for (int ks = 0; ks < 8; ks++){
        int kk = ks << 3;
        aq[ks][0] = __float_as_uint(Qs[mr*QST     + kk + tig]);
        aq[ks][1] = __float_as_uint(Qs[(mr+8)*QST + kk + tig]);
        aq[ks][2] = __float_as_uint(Qs[mr*QST     + kk + tig + 4]);
        aq[ks][3] = __float_as_uint(Qs[(mr+8)*QST + kk + tig + 4]);
    }

    float accO[8][4];
    #pragma unroll
    for (int nt = 0; nt < 8; nt++)
        #pragma unroll
        for (int q = 0; q < 4; q++) accO[nt][q] = 0.f;
    float mrow0 = -1e30f, mrow1 = -1e30f, lrow0 = 0.f, lrow1 = 0.f;
    const float scale = 1.0f / 1024.0f;

    for (int n0 = 0; n0 < SQ; n0 += 64){
        for (int i = tid; i < 64*16; i += 128){
            int r = i >> 4, c4 = i & 15;
            *(float4*)&Ks[r*KST + c4*4] = *(const float4*)&Kbh[(size_t)r * SQ + n0 + c4*4];
            *(float4*)&Vs[r*KST + c4*4] = *(const float4*)&Vbh[(size_t)(n0 + r) * DHQ + c4*4];
        }
        __syncthreads();

        float sacc[8][4];
        #pragma unroll
        for (int nt = 0; nt < 8; nt++)
            #pragma unroll
            for (int q = 0; q < 4; q++) sacc[nt][q] = 0.f;
        #pragma unroll
        for (int ks = 0; ks < 8; ks++){
            int kk = ks << 3;
            uint32_t bf[8][2];
            #pragma unroll
            for (int nt = 0; nt < 8; nt++){
                int nr = nt*8 + grp;
                bf[nt][0] = __float_as_uint(Ks[(kk + tig)*KST     + nr]);
                bf[nt][1] = __float_as_uint(Ks[(kk + tig + 4)*KST + nr]);
            }
            #pragma unroll
            for (int nt = 0; nt < 8; nt++)
                mma_tf32(sacc[nt], aq[ks], bf[nt]);
        }

        float mx0 = -1e30f, mx1 = -1e30f;
        #pragma unroll
        for (int nt = 0; nt < 8; nt++){
            sacc[nt][0] *= scale; sacc[nt][1] *= scale;
            sacc[nt][2] *= scale; sacc[nt][3] *= scale;
            mx0 = fmaxf(mx0, fmaxf(sacc[nt][0], sacc[nt][1]));
            mx1 = fmaxf(mx1, fmaxf(sacc[nt][2], sacc[nt][3]));
        }
        mx0 = fmaxf(mx0, __shfl_xor_sync(0xffffffffu, mx0, 1));
        mx0 = fmaxf(mx0, __shfl_xor_sync(0xffffffffu, mx0, 2));
        mx1 = fmaxf(mx1, __shfl_xor_sync(0xffffffffu, mx1, 1));
        mx1 = fmaxf(mx1, __shfl_xor_sync(0xffffffffu, mx1, 2));
        float mn0 = fmaxf(mrow0, mx0), mn1 = fmaxf(mrow1, mx1);
        float al0 = __expf(mrow0 - mn0), al1 = __expf(mrow1 - mn1);
        mrow0 = mn0; mrow1 = mn1;

        float ps0 = 0.f, ps1 = 0.f;
        #pragma unroll
        for (int nt = 0; nt < 8; nt++){
            float p0 = __expf(sacc[nt][0] - mn0);
            float p1 = __expf(sacc[nt][1] - mn0);
            float p2 = __expf(sacc[nt][2] - mn1);
            float p3 = __expf(sacc[nt][3] - mn1);
            ps0 += p0 + p1; ps1 += p2 + p3;
            int col = nt*8 + tig*2;
            *(float2*)&Ps[mr*QST + col]     = make_float2(rnd_tf32(p0), rnd_tf32(p1));
            *(float2*)&Ps[(mr+8)*QST + col] = make_float2(rnd_tf32(p2), rnd_tf32(p3));
        }
        ps0 += __shfl_xor_sync(0xffffffffu, ps0, 1);
        ps0 += __shfl_xor_sync(0xffffffffu, ps0, 2);
        ps1 += __shfl_xor_sync(0xffffffffu, ps1, 1);
        ps1 += __shfl_xor_sync(0xffffffffu, ps1, 2);
        lrow0 = lrow0 * al0 + ps0;
        lrow1 = lrow1 * al1 + ps1;
        #pragma unroll
        for (int nt = 0; nt < 8; nt++){
            accO[nt][0] *= al0; accO[nt][1] *= al0;
            accO[nt][2] *= al1; accO[nt][3] *= al1;
        }
        __syncwarp();

        #pragma unroll
        for (int ks = 0; ks < 8; ks++){
            int kk = ks << 3;
            uint32_t ap[4], bf[8][2];
            ap[0] = __float_as_uint(Ps[mr*QST     + kk + tig]);
            ap[1] = __float_as_uint(Ps[(mr+8)*QST + kk + tig]);
            ap[2] = __float_as_uint(Ps[mr*QST     + kk + tig + 4]);
            ap[3] = __float_as_uint(Ps[(mr+8)*QST + kk + tig + 4]);
            #pragma unroll
            for (int nt = 0; nt < 8; nt++){
                int nr = nt*8 + grp;
                bf[nt][0] = __float_as_uint(Vs[(kk + tig)*KST     + nr]);
                bf[nt][1] = __float_as_uint(Vs[(kk + tig + 4)*KST + nr]);
            }
            #pragma unroll
            for (int nt = 0; nt < 8; nt++)
                mma_tf32(accO[nt], ap, bf[nt]);
        }
        __syncthreads();
    }

    float inv0 = 1.0f / lrow0, inv1 = 1.0f / lrow1;
    int row0 = m0 + mr, row1 = row0 + 8;
    #pragma unroll
    for (int nt = 0; nt < 8; nt++){
        int e = nt*8 + tig*2;
        *(float2*)&hc[((size_t)b*SQ + row0)*DQ + h*64 + e] =
            make_float2(rnd_tf32(accO[nt][0]*inv0), rnd_tf32(accO[nt][1]*inv0));
        *(float2*)&hc[((size_t)b*SQ + row1)*DQ + h*64 + e] =
            make_float2(rnd_tf32(accO[nt][2]*inv1), rnd_tf32(accO[nt][3]*inv1));
    }
}

// ---------------- launch ----------------
extern "C" void kernel_launch(void* const* d_in, const int* in_sizes, int n_in,
                              void* d_out, int out_size)
{
    const float* x      = (const float*)d_in[0];
    const float* W_Q    = (const float*)d_in[1];
    const float* W_K    = (const float*)d_in[2];
    const float* W_V    = (const float*)d_in[3];
    const float* W_O    = (const float*)d_in[4];
    const float* W_up   = (const float*)d_in[5];
    const float* b_up   = (const float*)d_in[6];
    const float* W_down = (const float*)d_in[7];
    const float* b_down = (const float*)d_in[8];
    const float* gamma1 = (const float*)d_in[9];
    const float* beta1  = (const float*)d_in[10];
    const float* gamma2 = (const float*)d_in[11];
    const float* beta2  = (const float*)d_in[12];
    float* out = (float*)d_out;

    float *u, *Qp, *Krp, *Vp, *hcp, *z1, *v1, *v3, *WOt, *Wupt, *Wdnt, *Wqkv;
    cudaGetSymbolAddress((void**)&u,    g_u);
    cudaGetSymbolAddress((void**)&Qp,   g_Q);
    cudaGetSymbolAddress((void**)&Krp,  g_Kr);
    cudaGetSymbolAddress((void**)&Vp,   g_V);
    cudaGetSymbolAddress((void**)&hcp,  g_hc);
    cudaGetSymbolAddress((void**)&z1,   g_z1);
    cudaGetSymbolAddress((void**)&v1,   g_v1);
    cudaGetSymbolAddress((void**)&v3,   g_v3);
    cudaGetSymbolAddress((void**)&WOt,  g_WOt);
    cudaGetSymbolAddress((void**)&Wupt, g_Wupt);
    cudaGetSymbolAddress((void**)&Wdnt, g_Wdnt);
    cudaGetSymbolAddress((void**)&Wqkv, g_Wqkv);

    cudaFuncSetAttribute((const void*)mma_gemm<1>, cudaFuncAttributeMaxDynamicSharedMemorySize, GEMM_SMEM);
    cudaFuncSetAttribute((const void*)mma_gemm<2>, cudaFuncAttributeMaxDynamicSharedMemorySize, GEMM_SMEM);
    cudaFuncSetAttribute((const void*)mma_gemm<3>, cudaFuncAttributeMaxDynamicSharedMemorySize, GEMM_SMEM);
    cudaFuncSetAttribute((const void*)mma_gemm<6>, cudaFuncAttributeMaxDynamicSharedMemorySize, GEMM_SMEM);
    cudaFuncSetAttribute((const void*)attn_tc,     cudaFuncAttributeMaxDynamicSharedMemorySize, ATTN_SMEM);

    // prep
    round_copy_qkv<<<1024, 256>>>(W_Q, W_K, W_V, Wqkv);
    transpose_kernel<<<dim3(DQ/32, DQ/32), dim3(32,8)>>>(W_O, WOt, DQ, DQ);
    transpose_updn_kernel<<<dim3(FQ/32, DQ/32, 2), dim3(32,8)>>>(W_up, Wupt, W_down, Wdnt);
    ln_kernel<<<MQ, 256>>>(x, gamma1, beta1, u);

    // fused QKV projection
    mma_gemm<6><<<dim3(3*DQ/128, MQ/256), 512, GEMM_SMEM>>>(u, Wqkv, Qp, MQ, 3*DQ, DQ, Krp, Vp);
    // tensor-core flash attention
    attn_tc<<<dim3(SQ/64, BQ*HQ), 128, ATTN_SMEM>>>(Qp, Krp, Vp, hcp);
    // O projection + residual x
    mma_gemm<1><<<dim3(DQ/128, MQ/256), 512, GEMM_SMEM>>>(hcp, WOt, z1, MQ, DQ, DQ, nullptr, x);
    // LN2
    ln_kernel<<<MQ, 256>>>(z1, gamma2, beta2, v1);
    // FFN up + bias + exact GELU
    mma_gemm<2><<<dim3(FQ/128, MQ/256), 512, GEMM_SMEM>>>(v1, Wupt, v3, MQ, FQ, DQ, b_up, nullptr);
    // FFN down + bias + residual z1 -> out
    mma_gemm<3><<<dim3(DQ/128, MQ/256), 512, GEMM_SMEM>>>(v3, Wdnt, out, MQ, DQ, FQ, b_down, z1);
}